// round 5
// baseline (speedup 1.0000x reference)
#include <cuda_runtime.h>
#include <cuda_bf16.h>

#define NBAT 1024
#define TT   128

__device__ __forceinline__ float dot12(const float4* a, const float4* b) {
    float4 a0 = a[0], a1 = a[1], a2 = a[2];
    float4 b0 = b[0], b1 = b[1], b2 = b[2];
    return a0.x*b0.x + a0.y*b0.y + a0.z*b0.z + a0.w*b0.w
         + a1.x*b1.x + a1.y*b1.y + a1.z*b1.z + a1.w*b1.w
         + a2.x*b2.x + a2.y*b2.y + a2.z*b2.z + a2.w*b2.w;
}

__global__ __launch_bounds__(256, 6) void lqr_kernel(
    const float* __restrict__ x_init,     // [NB, 12]
    const float* __restrict__ current_u,  // [NB, T, 4]
    const float* __restrict__ Qg,         // [NB, T, 16, 16]
    const float* __restrict__ pg,         // [NB, T, 16]
    const float* __restrict__ Ag,         // [NB, T, 12, 12]
    const float* __restrict__ Bg,         // [NB, T, 12, 4]
    float* __restrict__ out)              // [xs | us | cost]
{
    const int b   = blockIdx.x;
    const int tid = threadIdx.x;
    const size_t bT = (size_t)b * TT;

    // backward-pass shared state
    __shared__ __align__(16) float sFT[16 * 12];   // FT[j][k] = F[k][j]; fwd: A rows (144) | B rows (48)
    __shared__ __align__(16) float sp[16];
    __shared__ __align__(16) float sV[12 * 12];
    __shared__ __align__(16) float sv[12];
    __shared__ __align__(16) float sMT[16 * 12];   // MT[j][i] = (V F)[i][j]
    __shared__ __align__(16) float sQt[256];
    __shared__ __align__(16) float sqt[16];
    __shared__ __align__(16) float sKt[4 * 12];
    __shared__ __align__(16) float skt[4];
    __shared__ __align__(16) float sk_all[TT * 4];
    // forward-pass shared state
    __shared__ __align__(16) float scu[4];
    __shared__ __align__(16) float sxu[16];
    __shared__ __align__(16) float sxn[12];
    __shared__ float sred[8];

    if (tid < 144) sV[tid] = 0.f;
    if (tid < 12)  sv[tid] = 0.f;

    // ---- prologue: prefetch step T-1 ----
    float rQ, rQn, rX = 0.f;
    rQn = Qg[(bT + TT - 1) * 256 + tid];
    if (tid < 144)      rX = Ag[(bT + TT - 1) * 144 + tid];
    else if (tid < 192) rX = Bg[(bT + TT - 1) * 48 + (tid - 144)];
    else if (tid < 208) rX = pg[(bT + TT - 1) * 16 + (tid - 192)];

    // ================= BACKWARD SCAN =================
    for (int t = TT - 1; t >= 0; --t) {
        rQ = rQn;
        // stage FT (transposed F), p
        if (tid < 144) {
            int k = tid / 12, j = tid - k * 12;
            sFT[j * 12 + k] = rX;
        } else if (tid < 192) {
            int idx = tid - 144, k = idx >> 2, c = idx & 3;
            sFT[(12 + c) * 12 + k] = rX;
        } else if (tid < 208) {
            sp[tid - 192] = rX;
        }
        // prefetch step t-1
        if (t > 0) {
            rQn = Qg[(bT + t - 1) * 256 + tid];
            if (tid < 144)      rX = Ag[(bT + t - 1) * 144 + tid];
            else if (tid < 192) rX = Bg[(bT + t - 1) * 48 + (tid - 144)];
            else if (tid < 208) rX = pg[(bT + t - 1) * 16 + (tid - 192)];
        }
        __syncthreads();  // s1

        // phase 2: MT[j][i] = dot(V row i, FT row j);  qt = p + FT v
        if (tid < 192) {
            int i = tid >> 4, j = tid & 15;
            float s = dot12((const float4*)&sV[i * 12], (const float4*)&sFT[j * 12]);
            sMT[j * 12 + i] = s;
        } else if (tid < 208) {
            int j = tid - 192;
            float s = sp[j] + dot12((const float4*)&sFT[j * 12], (const float4*)sv);
            sqt[j] = s;
        }
        __syncthreads();  // s2

        // phase 3: Qt[i][j] = Q0 + dot(FT row i, MT row j)
        {
            int i = tid >> 4, j = tid & 15;
            sQt[tid] = rQ + dot12((const float4*)&sFT[i * 12], (const float4*)&sMT[j * 12]);
        }
        __syncthreads();  // s3

        // phase 4: Kt = -Quu^-1 Qux, kt = -Quu^-1 qu  (cofactors in-register)
        if (tid < 52) {
            int a = (tid < 48) ? (tid / 12) : (tid - 48);
            float q[4][4];
            #pragma unroll
            for (int r = 0; r < 4; ++r) {
                float4 qr = *(const float4*)&sQt[(12 + r) * 16 + 12];
                q[r][0] = qr.x; q[r][1] = qr.y; q[r][2] = qr.z; q[r][3] = qr.w;
            }
            int c0 = (a == 0) ? 1 : 0, c1 = (a <= 1) ? 2 : 1, c2 = (a <= 2) ? 3 : 2;
            float cof[4];
            #pragma unroll
            for (int bb = 0; bb < 4; ++bb) {
                int r0 = (bb == 0) ? 1 : 0, r1 = (bb <= 1) ? 2 : 1, r2 = (bb <= 2) ? 3 : 2;
                float m = q[r0][c0] * (q[r1][c1] * q[r2][c2] - q[r1][c2] * q[r2][c1])
                        - q[r0][c1] * (q[r1][c0] * q[r2][c2] - q[r1][c2] * q[r2][c0])
                        + q[r0][c2] * (q[r1][c0] * q[r2][c1] - q[r1][c1] * q[r2][c0]);
                cof[bb] = ((a + bb) & 1) ? -m : m;
            }
            float det = q[0][a] * cof[0] + q[1][a] * cof[1] + q[2][a] * cof[2] + q[3][a] * cof[3];
            float ninvd = -1.f / det;
            if (tid < 48) {
                int j = tid - a * 12;
                float s = cof[0] * sQt[12 * 16 + j] + cof[1] * sQt[13 * 16 + j]
                        + cof[2] * sQt[14 * 16 + j] + cof[3] * sQt[15 * 16 + j];
                sKt[a * 12 + j] = ninvd * s;
            } else {
                float s = cof[0] * sqt[12] + cof[1] * sqt[13] + cof[2] * sqt[14] + cof[3] * sqt[15];
                float kk = ninvd * s;
                skt[a] = kk;
                sk_all[t * 4 + a] = kk;
            }
        }
        __syncthreads();  // s4

        // phase 5: Vn = Qxx + Qxu Kt ; vn = qx + Qxu kt  (uses Quu Kt = -Qux)
        if (tid < 36) {
            int i = tid / 3, jq = tid - (tid / 3) * 3;
            float4 acc = *(const float4*)&sQt[i * 16 + jq * 4];
            float4 qxu = *(const float4*)&sQt[i * 16 + 12];
            float4 k0 = *(const float4*)&sKt[0 * 12 + jq * 4];
            float4 k1 = *(const float4*)&sKt[1 * 12 + jq * 4];
            float4 k2 = *(const float4*)&sKt[2 * 12 + jq * 4];
            float4 k3 = *(const float4*)&sKt[3 * 12 + jq * 4];
            acc.x += qxu.x * k0.x + qxu.y * k1.x + qxu.z * k2.x + qxu.w * k3.x;
            acc.y += qxu.x * k0.y + qxu.y * k1.y + qxu.z * k2.y + qxu.w * k3.y;
            acc.z += qxu.x * k0.z + qxu.y * k1.z + qxu.z * k2.z + qxu.w * k3.z;
            acc.w += qxu.x * k0.w + qxu.y * k1.w + qxu.z * k2.w + qxu.w * k3.w;
            *(float4*)&sV[i * 12 + jq * 4] = acc;
        } else if (tid < 48) {
            int i = tid - 36;
            sv[i] = sqt[i] + sQt[i * 16 + 12] * skt[0] + sQt[i * 16 + 13] * skt[1]
                           + sQt[i * 16 + 14] * skt[2] + sQt[i * 16 + 15] * skt[3];
        }
        // next-iter s1 orders these writes before their readers
    }

    // ================= FORWARD SCAN =================
    float cost = 0.f;
    if (tid < 12) sxn[tid] = x_init[b * 12 + tid];

    // prefetch t = 0 (sFT reused as A rows | B rows, row-major)
    rQn = Qg[bT * 256 + tid];
    if (tid < 144)      rX = Ag[bT * 144 + tid];
    else if (tid < 192) rX = Bg[bT * 48 + (tid - 144)];
    else if (tid < 208) rX = pg[bT * 16 + (tid - 192)];
    else if (tid < 212) rX = current_u[bT * 4 + (tid - 208)];

    float* out_xs   = out;
    float* out_us   = out + (size_t)NBAT * TT * 12;
    float* out_cost = out_us + (size_t)NBAT * TT * 4;

    for (int t = 0; t < TT; ++t) {
        rQ = rQn;
        if (tid < 192)      sFT[tid] = rX;
        else if (tid < 208) sp[tid - 192] = rX;
        else if (tid < 212) scu[tid - 208] = rX;
        if (t + 1 < TT) {
            rQn = Qg[(bT + t + 1) * 256 + tid];
            if (tid < 144)      rX = Ag[(bT + t + 1) * 144 + tid];
            else if (tid < 192) rX = Bg[(bT + t + 1) * 48 + (tid - 144)];
            else if (tid < 208) rX = pg[(bT + t + 1) * 16 + (tid - 192)];
            else if (tid < 212) rX = current_u[(bT + t + 1) * 4 + (tid - 208)];
        }
        __syncthreads();  // f1

        if (tid < 12) {
            float xv = sxn[tid];
            sxu[tid] = xv;
            out_xs[(bT + t) * 12 + tid] = xv;
        } else if (tid < 16) {
            int a = tid - 12;
            float u = scu[a] + sk_all[t * 4 + a];
            sxu[tid] = u;
            out_us[(bT + t) * 4 + a] = u;
        }
        __syncthreads();  // f2

        // cost partials (per-thread Q element) + warp reduce
        {
            int i = tid >> 4, j = tid & 15;
            float c = 0.5f * rQ * sxu[i] * sxu[j];
            if (i == 0) c += sp[j] * sxu[j];
            #pragma unroll
            for (int off = 16; off; off >>= 1)
                c += __shfl_down_sync(0xffffffffu, c, off);
            if ((tid & 31) == 0) sred[tid >> 5] = c;
        }
        // dynamics: xnext = A x + B u
        if (tid >= 64 && tid < 76) {
            int i = tid - 64;
            const float4* Ar = (const float4*)&sFT[i * 12];
            float4 a0 = Ar[0], a1 = Ar[1], a2 = Ar[2];
            float4 b0 = *(const float4*)&sFT[144 + i * 4];
            const float4* X = (const float4*)sxu;
            float4 x0 = X[0], x1 = X[1], x2 = X[2], x3 = X[3];
            float s = a0.x*x0.x + a0.y*x0.y + a0.z*x0.z + a0.w*x0.w
                    + a1.x*x1.x + a1.y*x1.y + a1.z*x1.z + a1.w*x1.w
                    + a2.x*x2.x + a2.y*x2.y + a2.z*x2.z + a2.w*x2.w
                    + b0.x*x3.x + b0.y*x3.y + b0.z*x3.z + b0.w*x3.w;
            sxn[i] = s;
        }
        __syncthreads();  // f3

        if (tid == 0) {
            cost += sred[0] + sred[1] + sred[2] + sred[3]
                  + sred[4] + sred[5] + sred[6] + sred[7];
        }
    }

    if (tid == 0) out_cost[b] = cost;
}

extern "C" void kernel_launch(void* const* d_in, const int* in_sizes, int n_in,
                              void* d_out, int out_size) {
    // metadata order: x_init, current_x(unused), current_u, Q, p, A, Bmat, time(unused)
    const float* x_init    = (const float*)d_in[0];
    const float* current_u = (const float*)d_in[2];
    const float* Q         = (const float*)d_in[3];
    const float* p         = (const float*)d_in[4];
    const float* A         = (const float*)d_in[5];
    const float* Bmat      = (const float*)d_in[6];
    float* out = (float*)d_out;

    lqr_kernel<<<NBAT, 256>>>(x_init, current_u, Q, p, A, Bmat, out);
}

// round 6
// speedup vs baseline: 1.3905x; 1.3905x over previous
#include <cuda_runtime.h>
#include <cuda_bf16.h>

#define NBAT 1024
#define TT   128
#define RS   480   // ring slot stride (floats): 256 Q + 212 F/p/cu + pad

__device__ __forceinline__ float dot12(const float4* a, const float4* b) {
    float4 a0 = a[0], a1 = a[1], a2 = a[2];
    float4 b0 = b[0], b1 = b[1], b2 = b[2];
    return a0.x*b0.x + a0.y*b0.y + a0.z*b0.z + a0.w*b0.w
         + a1.x*b1.x + a1.y*b1.y + a1.z*b1.z + a1.w*b1.w
         + a2.x*b2.x + a2.y*b2.y + a2.z*b2.z + a2.w*b2.w;
}

__device__ __forceinline__ void cpa4(unsigned s, const float* g) {
    asm volatile("cp.async.ca.shared.global [%0], [%1], 4;" :: "r"(s), "l"(g));
}
__device__ __forceinline__ void cpa_commit() { asm volatile("cp.async.commit_group;"); }
__device__ __forceinline__ void cpa_wait3() { asm volatile("cp.async.wait_group 3;" ::: "memory"); }

// Issue one time-step's inputs into a ring slot. Thread tid owns:
//   slot[tid]      = Q element tid
//   slot[256+tid]  = A (tid<144) | B (144..191) | p (192..207) | cu (208..211, fwd only)
__device__ __forceinline__ void issue_step(
    unsigned slot_u32, int tid, size_t bt,
    const float* __restrict__ Qg, const float* __restrict__ Ag,
    const float* __restrict__ Bg, const float* __restrict__ pg,
    const float* __restrict__ cug)
{
    cpa4(slot_u32 + tid * 4u, Qg + bt * 256 + tid);
    if (tid < 144)       cpa4(slot_u32 + (256u + tid) * 4u, Ag + bt * 144 + tid);
    else if (tid < 192)  cpa4(slot_u32 + (256u + tid) * 4u, Bg + bt * 48 + (tid - 144));
    else if (tid < 208)  cpa4(slot_u32 + (256u + tid) * 4u, pg + bt * 16 + (tid - 192));
    else if (cug != nullptr && tid < 212)
                         cpa4(slot_u32 + (256u + tid) * 4u, cug + bt * 4 + (tid - 208));
    cpa_commit();
}

__global__ __launch_bounds__(256, 7) void lqr_kernel(
    const float* __restrict__ x_init,     // [NB, 12]
    const float* __restrict__ current_u,  // [NB, T, 4]
    const float* __restrict__ Qg,         // [NB, T, 16, 16]
    const float* __restrict__ pg,         // [NB, T, 16]
    const float* __restrict__ Ag,         // [NB, T, 12, 12]
    const float* __restrict__ Bg,         // [NB, T, 12, 4]
    float* __restrict__ out)              // [xs | us | cost]
{
    const int b   = blockIdx.x;
    const int tid = threadIdx.x;
    const size_t bT = (size_t)b * TT;

    __shared__ __align__(16) float ring[4 * RS];
    __shared__ __align__(16) float sFT[16 * 12];   // bwd: FT[j][k]; fwd: A rows | B rows
    __shared__ __align__(16) float sp[16];
    __shared__ __align__(16) float sV[12 * 12];
    __shared__ __align__(16) float sv[12];
    __shared__ __align__(16) float sMT[16 * 12];
    __shared__ __align__(16) float sQt[256];
    __shared__ __align__(16) float sqt[16];
    __shared__ __align__(16) float sKt[4 * 12];
    __shared__ __align__(16) float skt[4];
    __shared__ __align__(16) float sk_all[TT * 4];
    __shared__ __align__(16) float scu[4];
    __shared__ __align__(16) float sxu[16];
    __shared__ __align__(16) float sxn[12];
    __shared__ float sred[8];

    const unsigned ring_u32 = (unsigned)__cvta_generic_to_shared(ring);

    if (tid < 144) sV[tid] = 0.f;
    if (tid < 12)  sv[tid] = 0.f;

    // ---- prologue: fill ring with steps T-1 .. T-4 (slots 0..3, FIFO oldest first) ----
    #pragma unroll
    for (int d = 0; d < 4; ++d)
        issue_step(ring_u32 + (unsigned)(d * RS * 4), tid, bT + (TT - 1 - d),
                   Qg, Ag, Bg, pg, nullptr);

    // ================= BACKWARD SCAN =================
    for (int t = TT - 1; t >= 0; --t) {
        float* slot = &ring[((TT - 1 - t) & 3) * RS];
        const unsigned slot_u32 = ring_u32 + (unsigned)(((TT - 1 - t) & 3) * RS * 4);

        cpa_wait3();   // my own elements for step t are resident

        // stage (each thread reads ONLY its own ring elements)
        float rQ = slot[tid];
        if (tid < 144) {
            int k = tid / 12, j = tid - k * 12;
            sFT[j * 12 + k] = slot[256 + tid];
        } else if (tid < 192) {
            int idx = tid - 144, k = idx >> 2, c = idx & 3;
            sFT[(12 + c) * 12 + k] = slot[256 + tid];
        } else if (tid < 208) {
            sp[tid - 192] = slot[256 + tid];
        }

        // refill this slot with step t-4 (empty group to keep wait count invariant)
        if (t >= 4) issue_step(slot_u32, tid, bT + t - 4, Qg, Ag, Bg, pg, nullptr);
        else        cpa_commit();
        __syncthreads();  // s1: staged data + prev-iter sV/sv visible

        // phase 2: MT[j][i] = dot(V row i, FT row j);  qt = p + FT v
        if (tid < 192) {
            int i = tid >> 4, j = tid & 15;
            sMT[j * 12 + i] = dot12((const float4*)&sV[i * 12], (const float4*)&sFT[j * 12]);
        } else if (tid < 208) {
            int j = tid - 192;
            sqt[j] = sp[j] + dot12((const float4*)&sFT[j * 12], (const float4*)sv);
        }
        __syncthreads();  // s2

        // phase 3: Qt[i][j] = Q0 + dot(FT row i, MT row j)
        {
            int i = tid >> 4, j = tid & 15;
            sQt[tid] = rQ + dot12((const float4*)&sFT[i * 12], (const float4*)&sMT[j * 12]);
        }
        __syncthreads();  // s3

        // phase 4: Kt = -Quu^-1 Qux, kt = -Quu^-1 qu (cofactors in-register)
        if (tid < 52) {
            int a = (tid < 48) ? (tid / 12) : (tid - 48);
            float q[4][4];
            #pragma unroll
            for (int r = 0; r < 4; ++r) {
                float4 qr = *(const float4*)&sQt[(12 + r) * 16 + 12];
                q[r][0] = qr.x; q[r][1] = qr.y; q[r][2] = qr.z; q[r][3] = qr.w;
            }
            int c0 = (a == 0) ? 1 : 0, c1 = (a <= 1) ? 2 : 1, c2 = (a <= 2) ? 3 : 2;
            float cof[4];
            #pragma unroll
            for (int bb = 0; bb < 4; ++bb) {
                int r0 = (bb == 0) ? 1 : 0, r1 = (bb <= 1) ? 2 : 1, r2 = (bb <= 2) ? 3 : 2;
                float m = q[r0][c0] * (q[r1][c1] * q[r2][c2] - q[r1][c2] * q[r2][c1])
                        - q[r0][c1] * (q[r1][c0] * q[r2][c2] - q[r1][c2] * q[r2][c0])
                        + q[r0][c2] * (q[r1][c0] * q[r2][c1] - q[r1][c1] * q[r2][c0]);
                cof[bb] = ((a + bb) & 1) ? -m : m;
            }
            float det = q[0][a] * cof[0] + q[1][a] * cof[1] + q[2][a] * cof[2] + q[3][a] * cof[3];
            float ninvd = -1.f / det;
            if (tid < 48) {
                int j = tid - a * 12;
                float s = cof[0] * sQt[12 * 16 + j] + cof[1] * sQt[13 * 16 + j]
                        + cof[2] * sQt[14 * 16 + j] + cof[3] * sQt[15 * 16 + j];
                sKt[a * 12 + j] = ninvd * s;
            } else {
                float s = cof[0] * sqt[12] + cof[1] * sqt[13] + cof[2] * sqt[14] + cof[3] * sqt[15];
                float kk = ninvd * s;
                skt[a] = kk;
                sk_all[t * 4 + a] = kk;
            }
        }
        __syncthreads();  // s4

        // phase 5: Vn = Qxx + Qxu Kt ; vn = qx + Qxu kt  (uses Quu Kt = -Qux)
        if (tid < 36) {
            int i = tid / 3, jq = tid - (tid / 3) * 3;
            float4 acc = *(const float4*)&sQt[i * 16 + jq * 4];
            float4 qxu = *(const float4*)&sQt[i * 16 + 12];
            float4 k0 = *(const float4*)&sKt[0 * 12 + jq * 4];
            float4 k1 = *(const float4*)&sKt[1 * 12 + jq * 4];
            float4 k2 = *(const float4*)&sKt[2 * 12 + jq * 4];
            float4 k3 = *(const float4*)&sKt[3 * 12 + jq * 4];
            acc.x += qxu.x * k0.x + qxu.y * k1.x + qxu.z * k2.x + qxu.w * k3.x;
            acc.y += qxu.x * k0.y + qxu.y * k1.y + qxu.z * k2.y + qxu.w * k3.y;
            acc.z += qxu.x * k0.z + qxu.y * k1.z + qxu.z * k2.z + qxu.w * k3.z;
            acc.w += qxu.x * k0.w + qxu.y * k1.w + qxu.z * k2.w + qxu.w * k3.w;
            *(float4*)&sV[i * 12 + jq * 4] = acc;
        } else if (tid < 48) {
            int i = tid - 36;
            sv[i] = sqt[i] + sQt[i * 16 + 12] * skt[0] + sQt[i * 16 + 13] * skt[1]
                           + sQt[i * 16 + 14] * skt[2] + sQt[i * 16 + 15] * skt[3];
        }
        // next-iter s1 orders these writes before their readers
    }

    // ================= FORWARD SCAN =================
    float cost = 0.f;
    if (tid < 12) sxn[tid] = x_init[b * 12 + tid];

    // prologue: steps 0..3 into slots 0..3 (oldest-first FIFO order)
    #pragma unroll
    for (int d = 0; d < 4; ++d)
        issue_step(ring_u32 + (unsigned)(d * RS * 4), tid, bT + d,
                   Qg, Ag, Bg, pg, current_u);

    float* out_xs   = out;
    float* out_us   = out + (size_t)NBAT * TT * 12;
    float* out_cost = out_us + (size_t)NBAT * TT * 4;

    for (int t = 0; t < TT; ++t) {
        float* slot = &ring[(t & 3) * RS];
        const unsigned slot_u32 = ring_u32 + (unsigned)((t & 3) * RS * 4);

        cpa_wait3();

        float rQ = slot[tid];
        if (tid < 192)      sFT[tid]       = slot[256 + tid];  // A rows | B rows, row-major
        else if (tid < 208) sp[tid - 192]  = slot[256 + tid];
        else if (tid < 212) scu[tid - 208] = slot[256 + tid];

        if (t + 4 < TT) issue_step(slot_u32, tid, bT + t + 4, Qg, Ag, Bg, pg, current_u);
        else            cpa_commit();
        __syncthreads();  // f1

        if (tid < 12) {
            float xv = sxn[tid];
            sxu[tid] = xv;
            out_xs[(bT + t) * 12 + tid] = xv;
        } else if (tid < 16) {
            int a = tid - 12;
            float u = scu[a] + sk_all[t * 4 + a];
            sxu[tid] = u;
            out_us[(bT + t) * 4 + a] = u;
        }
        __syncthreads();  // f2

        // cost partials (per-thread Q element) + warp reduce
        {
            int i = tid >> 4, j = tid & 15;
            float c = 0.5f * rQ * sxu[i] * sxu[j];
            if (i == 0) c += sp[j] * sxu[j];
            #pragma unroll
            for (int off = 16; off; off >>= 1)
                c += __shfl_down_sync(0xffffffffu, c, off);
            if ((tid & 31) == 0) sred[tid >> 5] = c;
        }
        // dynamics: xnext = A x + B u
        if (tid >= 64 && tid < 76) {
            int i = tid - 64;
            const float4* Ar = (const float4*)&sFT[i * 12];
            float4 a0 = Ar[0], a1 = Ar[1], a2 = Ar[2];
            float4 b0 = *(const float4*)&sFT[144 + i * 4];
            const float4* X = (const float4*)sxu;
            float4 x0 = X[0], x1 = X[1], x2 = X[2], x3 = X[3];
            float s = a0.x*x0.x + a0.y*x0.y + a0.z*x0.z + a0.w*x0.w
                    + a1.x*x1.x + a1.y*x1.y + a1.z*x1.z + a1.w*x1.w
                    + a2.x*x2.x + a2.y*x2.y + a2.z*x2.z + a2.w*x2.w
                    + b0.x*x3.x + b0.y*x3.y + b0.z*x3.z + b0.w*x3.w;
            sxn[i] = s;
        }
        __syncthreads();  // f3

        if (tid == 0) {
            cost += sred[0] + sred[1] + sred[2] + sred[3]
                  + sred[4] + sred[5] + sred[6] + sred[7];
        }
    }

    if (tid == 0) out_cost[b] = cost;
}

extern "C" void kernel_launch(void* const* d_in, const int* in_sizes, int n_in,
                              void* d_out, int out_size) {
    // metadata order: x_init, current_x(unused), current_u, Q, p, A, Bmat, time(unused)
    const float* x_init    = (const float*)d_in[0];
    const float* current_u = (const float*)d_in[2];
    const float* Q         = (const float*)d_in[3];
    const float* p         = (const float*)d_in[4];
    const float* A         = (const float*)d_in[5];
    const float* Bmat      = (const float*)d_in[6];
    float* out = (float*)d_out;

    lqr_kernel<<<NBAT, 256>>>(x_init, current_u, Q, p, A, Bmat, out);
}

// round 7
// speedup vs baseline: 1.6640x; 1.1967x over previous
#include <cuda_runtime.h>
#include <cuda_bf16.h>

#define NBAT 1024
#define TT   128
#define RS   480           // slot stride in floats (256 Q + 212 payload + pad)
#define NSLOT 5
#define SLOTB (RS * 4)     // 1920 bytes

__device__ __forceinline__ float dot12(const float4* a, const float4* b) {
    float4 a0 = a[0], a1 = a[1], a2 = a[2];
    float4 b0 = b[0], b1 = b[1], b2 = b[2];
    return a0.x*b0.x + a0.y*b0.y + a0.z*b0.z + a0.w*b0.w
         + a1.x*b1.x + a1.y*b1.y + a1.z*b1.z + a1.w*b1.w
         + a2.x*b2.x + a2.y*b2.y + a2.z*b2.z + a2.w*b2.w;
}

__device__ __forceinline__ void cpa4(unsigned s, const float* g) {
    asm volatile("cp.async.ca.shared.global [%0], [%1], 4;" :: "r"(s), "l"(g));
}
__device__ __forceinline__ void cpa16(unsigned s, const float* g) {
    asm volatile("cp.async.cg.shared.global [%0], [%1], 16;" :: "r"(s), "l"(g));
}
__device__ __forceinline__ void cpa_commit() { asm volatile("cp.async.commit_group;"); }
__device__ __forceinline__ void cpa_wait4()  { asm volatile("cp.async.wait_group 4;" ::: "memory"); }

__global__ __launch_bounds__(256, 7) void lqr_kernel(
    const float* __restrict__ x_init,     // [NB, 12]
    const float* __restrict__ current_u,  // [NB, T, 4]
    const float* __restrict__ Qg,         // [NB, T, 16, 16]
    const float* __restrict__ pg,         // [NB, T, 16]
    const float* __restrict__ Ag,         // [NB, T, 12, 12]
    const float* __restrict__ Bg,         // [NB, T, 12, 4]
    float* __restrict__ out)              // [xs | us | cost]
{
    const int b   = blockIdx.x;
    const int tid = threadIdx.x;
    const size_t bT = (size_t)b * TT;

    // Slot layout (floats): [0..255] Q row-major
    //   bwd: [256..447] FT (16 rows x 12, FT[j][k] = F[k][j])
    //   fwd: [256..399] A row-major, [400..447] B row-major
    //   [448..463] p ; [464..467] cu (fwd)
    __shared__ __align__(16) float ring[NSLOT * RS];
    __shared__ __align__(16) float sV[12 * 12];
    __shared__ __align__(16) float sv[12];
    __shared__ __align__(16) float sMT[16 * 12];
    __shared__ __align__(16) float sQt[256];
    __shared__ __align__(16) float sqt[16];
    __shared__ __align__(16) float sKt[4 * 12];
    __shared__ __align__(16) float skt[4];
    __shared__ __align__(16) float sk_all[TT * 4];
    __shared__ __align__(16) float sxu[16];
    __shared__ __align__(16) float sxn[12];
    __shared__ float sred[8];

    const unsigned ring_u32 = (unsigned)__cvta_generic_to_shared(ring);

    if (tid < 144) sV[tid] = 0.f;
    if (tid < 12)  sv[tid] = 0.f;

    // ---- per-thread bwd copy jobs (destination offsets loop-invariant) ----
    unsigned xdoff = 0; int xstr = 0;
    {
        if (tid < 144) { int k = tid / 12, j = tid - 12 * k; xdoff = (256u + j * 12 + k) * 4u; xstr = 144; }
        else if (tid < 192) { int idx = tid - 144, k = idx >> 2, c = idx & 3;
                              xdoff = (256u + (12 + c) * 12 + k) * 4u; xstr = 48; }
        else if (tid < 196) { int idx = tid - 192; xdoff = (448u + idx * 4) * 4u; xstr = 16; }
    }

    // ---- bwd prologue: fill slots 0..3 with steps T-1..T-4 ----
    #pragma unroll
    for (int d = 0; d < 4; ++d) {
        const size_t bt = bT + (TT - 1 - d);
        const unsigned fb = ring_u32 + (unsigned)(d * SLOTB);
        if (tid < 64)  cpa16(fb + tid * 16u, Qg + bt * 256 + tid * 4);
        if (tid < 144)      cpa4(fb + xdoff, Ag + bt * 144 + tid);
        else if (tid < 192) cpa4(fb + xdoff, Bg + bt * 48 + (tid - 144));
        else if (tid < 196) cpa16(fb + xdoff, pg + bt * 16 + (tid - 192) * 4);
        cpa_commit();
    }

    // main-loop src pointers start at step T-5
    const float* qsrc = Qg + (bT + TT - 5) * 256 + tid * 4;
    const float* xsrc = nullptr;
    if (tid < 144)      xsrc = Ag + (bT + TT - 5) * 144 + tid;
    else if (tid < 192) xsrc = Bg + (bT + TT - 5) * 48 + (tid - 144);
    else if (tid < 196) xsrc = pg + (bT + TT - 5) * 16 + (tid - 192) * 4;

    int use_f = 0;  // slot base in floats; fill slot = use + 4 (mod 5)

    // ================= BACKWARD SCAN =================
    for (int t = TT - 1; t >= 0; --t) {
        const float* sl = ring + use_f;

        // refill (step t-4) into slot (use+4)%5, issued before the wait
        {
            int fill_f = use_f + 4 * RS; if (fill_f >= NSLOT * RS) fill_f -= NSLOT * RS;
            const unsigned fb = ring_u32 + (unsigned)fill_f * 4u;
            if (t >= 4) {
                if (tid < 64)  cpa16(fb + tid * 16u, qsrc);
                if (tid < 192)      { if (xsrc) cpa4(fb + xdoff, xsrc); }
                else if (tid < 196) cpa16(fb + xdoff, xsrc);
                qsrc -= 256; xsrc -= xstr;
            }
            cpa_commit();
        }
        cpa_wait4();       // step t's group (oldest of <=5) complete
        __syncthreads();   // s1: slot t visible to all; prev sV/sv visible

        // phase 2: MT[j][i] = dot(V row i, FT row j); qt = p + FT v
        if (tid < 192) {
            int i = tid >> 4, j = tid & 15;
            sMT[j * 12 + i] = dot12((const float4*)&sV[i * 12], (const float4*)&sl[256 + j * 12]);
        } else if (tid < 208) {
            int j = tid - 192;
            sqt[j] = sl[448 + j] + dot12((const float4*)&sl[256 + j * 12], (const float4*)sv);
        }
        __syncthreads();  // s2

        // phase 3: Qt[i][j] = Q0 + dot(FT row i, MT row j)
        {
            int i = tid >> 4, j = tid & 15;
            sQt[tid] = sl[tid] + dot12((const float4*)&sl[256 + i * 12], (const float4*)&sMT[j * 12]);
        }
        __syncthreads();  // s3

        // phase 4: Kt = -Quu^-1 Qux, kt = -Quu^-1 qu (cofactors in-register)
        if (tid < 52) {
            int a = (tid < 48) ? (tid / 12) : (tid - 48);
            float q[4][4];
            #pragma unroll
            for (int r = 0; r < 4; ++r) {
                float4 qr = *(const float4*)&sQt[(12 + r) * 16 + 12];
                q[r][0] = qr.x; q[r][1] = qr.y; q[r][2] = qr.z; q[r][3] = qr.w;
            }
            int c0 = (a == 0) ? 1 : 0, c1 = (a <= 1) ? 2 : 1, c2 = (a <= 2) ? 3 : 2;
            float cof[4];
            #pragma unroll
            for (int bb = 0; bb < 4; ++bb) {
                int r0 = (bb == 0) ? 1 : 0, r1 = (bb <= 1) ? 2 : 1, r2 = (bb <= 2) ? 3 : 2;
                float m = q[r0][c0] * (q[r1][c1] * q[r2][c2] - q[r1][c2] * q[r2][c1])
                        - q[r0][c1] * (q[r1][c0] * q[r2][c2] - q[r1][c2] * q[r2][c0])
                        + q[r0][c2] * (q[r1][c0] * q[r2][c1] - q[r1][c1] * q[r2][c0]);
                cof[bb] = ((a + bb) & 1) ? -m : m;
            }
            float det = q[0][a] * cof[0] + q[1][a] * cof[1] + q[2][a] * cof[2] + q[3][a] * cof[3];
            float ninvd = -1.f / det;
            if (tid < 48) {
                int j = tid - a * 12;
                float s = cof[0] * sQt[12 * 16 + j] + cof[1] * sQt[13 * 16 + j]
                        + cof[2] * sQt[14 * 16 + j] + cof[3] * sQt[15 * 16 + j];
                sKt[a * 12 + j] = ninvd * s;
            } else {
                float s = cof[0] * sqt[12] + cof[1] * sqt[13] + cof[2] * sqt[14] + cof[3] * sqt[15];
                float kk = ninvd * s;
                skt[a] = kk;
                sk_all[t * 4 + a] = kk;
            }
        }
        __syncthreads();  // s4

        // phase 5: Vn = Qxx + Qxu Kt ; vn = qx + Qxu kt
        if (tid < 36) {
            int i = tid / 3, jq = tid - (tid / 3) * 3;
            float4 acc = *(const float4*)&sQt[i * 16 + jq * 4];
            float4 qxu = *(const float4*)&sQt[i * 16 + 12];
            float4 k0 = *(const float4*)&sKt[0 * 12 + jq * 4];
            float4 k1 = *(const float4*)&sKt[1 * 12 + jq * 4];
            float4 k2 = *(const float4*)&sKt[2 * 12 + jq * 4];
            float4 k3 = *(const float4*)&sKt[3 * 12 + jq * 4];
            acc.x += qxu.x * k0.x + qxu.y * k1.x + qxu.z * k2.x + qxu.w * k3.x;
            acc.y += qxu.x * k0.y + qxu.y * k1.y + qxu.z * k2.y + qxu.w * k3.y;
            acc.z += qxu.x * k0.z + qxu.y * k1.z + qxu.z * k2.z + qxu.w * k3.z;
            acc.w += qxu.x * k0.w + qxu.y * k1.w + qxu.z * k2.w + qxu.w * k3.w;
            *(float4*)&sV[i * 12 + jq * 4] = acc;
        } else if (tid < 48) {
            int i = tid - 36;
            sv[i] = sqt[i] + sQt[i * 16 + 12] * skt[0] + sQt[i * 16 + 13] * skt[1]
                           + sQt[i * 16 + 14] * skt[2] + sQt[i * 16 + 15] * skt[3];
        }
        use_f += RS; if (use_f >= NSLOT * RS) use_f = 0;
        // next-iter s1 orders sV/sv writes before their readers
    }

    // ================= FORWARD SCAN =================
    float cost = 0.f;
    if (tid < 12) sxn[tid] = x_init[b * 12 + tid];

    // fwd copy jobs: all float4
    unsigned fdoff = 0; int fstr = 0; const float* fsrc = nullptr;
    {
        const size_t bt = bT + 4;  // first refill step
        if (tid < 64)       { fdoff = tid * 16u;                     fsrc = Qg + bt * 256 + tid * 4;          fstr = 256; }
        else if (tid < 100) { int i = tid - 64;  fdoff = (256u + i * 4) * 4u; fsrc = Ag + bt * 144 + i * 4;   fstr = 144; }
        else if (tid < 112) { int i = tid - 100; fdoff = (400u + i * 4) * 4u; fsrc = Bg + bt * 48 + i * 4;    fstr = 48;  }
        else if (tid < 116) { int i = tid - 112; fdoff = (448u + i * 4) * 4u; fsrc = pg + bt * 16 + i * 4;    fstr = 16;  }
        else if (tid == 116){ fdoff = 464u * 4u;                     fsrc = current_u + bt * 4;               fstr = 4;   }
    }

    // fwd prologue: steps 0..3 into slots 0..3
    #pragma unroll
    for (int d = 0; d < 4; ++d) {
        const size_t bt = bT + d;
        const unsigned fb = ring_u32 + (unsigned)(d * SLOTB);
        if (tid < 64)       cpa16(fb + tid * 16u, Qg + bt * 256 + tid * 4);
        else if (tid < 100) cpa16(fb + fdoff, Ag + bt * 144 + (tid - 64) * 4);
        else if (tid < 112) cpa16(fb + fdoff, Bg + bt * 48 + (tid - 100) * 4);
        else if (tid < 116) cpa16(fb + fdoff, pg + bt * 16 + (tid - 112) * 4);
        else if (tid == 116) cpa16(fb + fdoff, current_u + bt * 4);
        cpa_commit();
    }

    float* out_xs   = out;
    float* out_us   = out + (size_t)NBAT * TT * 12;
    float* out_cost = out_us + (size_t)NBAT * TT * 4;

    use_f = 0;
    for (int t = 0; t < TT; ++t) {
        const float* sl = ring + use_f;

        {
            int fill_f = use_f + 4 * RS; if (fill_f >= NSLOT * RS) fill_f -= NSLOT * RS;
            const unsigned fb = ring_u32 + (unsigned)fill_f * 4u;
            if (t + 4 < TT) {
                if (fsrc) cpa16(fb + fdoff, fsrc);
                fsrc += fstr;
            }
            cpa_commit();
        }
        cpa_wait4();
        __syncthreads();  // f1

        if (tid < 12) {
            float xv = sxn[tid];
            sxu[tid] = xv;
            out_xs[(bT + t) * 12 + tid] = xv;
        } else if (tid < 16) {
            int a = tid - 12;
            float u = sl[464 + a] + sk_all[t * 4 + a];
            sxu[tid] = u;
            out_us[(bT + t) * 4 + a] = u;
        }
        __syncthreads();  // f2

        // cost partials (per-thread Q element) + warp reduce
        {
            int i = tid >> 4, j = tid & 15;
            float c = 0.5f * sl[tid] * sxu[i] * sxu[j];
            if (i == 0) c += sl[448 + j] * sxu[j];
            #pragma unroll
            for (int off = 16; off; off >>= 1)
                c += __shfl_down_sync(0xffffffffu, c, off);
            if ((tid & 31) == 0) sred[tid >> 5] = c;
        }
        // dynamics: xnext = A x + B u
        if (tid >= 64 && tid < 76) {
            int i = tid - 64;
            const float4* Ar = (const float4*)&sl[256 + i * 12];
            float4 a0 = Ar[0], a1 = Ar[1], a2 = Ar[2];
            float4 b0 = *(const float4*)&sl[400 + i * 4];
            const float4* X = (const float4*)sxu;
            float4 x0 = X[0], x1 = X[1], x2 = X[2], x3 = X[3];
            float s = a0.x*x0.x + a0.y*x0.y + a0.z*x0.z + a0.w*x0.w
                    + a1.x*x1.x + a1.y*x1.y + a1.z*x1.z + a1.w*x1.w
                    + a2.x*x2.x + a2.y*x2.y + a2.z*x2.z + a2.w*x2.w
                    + b0.x*x3.x + b0.y*x3.y + b0.z*x3.z + b0.w*x3.w;
            sxn[i] = s;
        }
        __syncthreads();  // f3

        if (tid == 0) {
            cost += sred[0] + sred[1] + sred[2] + sred[3]
                  + sred[4] + sred[5] + sred[6] + sred[7];
        }
        use_f += RS; if (use_f >= NSLOT * RS) use_f = 0;
    }

    if (tid == 0) out_cost[b] = cost;
}

extern "C" void kernel_launch(void* const* d_in, const int* in_sizes, int n_in,
                              void* d_out, int out_size) {
    // metadata order: x_init, current_x(unused), current_u, Q, p, A, Bmat, time(unused)
    const float* x_init    = (const float*)d_in[0];
    const float* current_u = (const float*)d_in[2];
    const float* Q         = (const float*)d_in[3];
    const float* p         = (const float*)d_in[4];
    const float* A         = (const float*)d_in[5];
    const float* Bmat      = (const float*)d_in[6];
    float* out = (float*)d_out;

    lqr_kernel<<<NBAT, 256>>>(x_init, current_u, Q, p, A, Bmat, out);
}